// round 10
// baseline (speedup 1.0000x reference)
#include <cuda_runtime.h>

#define FULL 0xffffffffu
typedef unsigned long long u64;

__device__ __forceinline__ u64 fma2(u64 a, u64 b, u64 c) {
    u64 d;
    asm("fma.rn.f32x2 %0, %1, %2, %3;" : "=l"(d) : "l"(a), "l"(b), "l"(c));
    return d;
}
__device__ __forceinline__ u64 pack2(float lo, float hi) {
    u64 d;
    asm("mov.b64 %0, {%1, %2};" : "=l"(d) : "f"(lo), "f"(hi));
    return d;
}
__device__ __forceinline__ float hadd2(u64 a) {
    float lo, hi;
    asm("mov.b64 {%0, %1}, %2;" : "=f"(lo), "=f"(hi) : "l"(a));
    return lo + hi;
}
// sigmoid(v) = 1 / (1 + 2^(-v*log2e))
__device__ __forceinline__ float fast_sig(float v) {
    float e;
    asm("ex2.approx.f32 %0, %1;" : "=f"(e) : "f"(v * -1.4426950408889634f));
    float r;
    asm("rcp.approx.f32 %0, %1;" : "=f"(r) : "f"(1.0f + e));
    return r;
}
// tanh(v) = 2/(1 + 2^(-2v*log2e)) - 1
__device__ __forceinline__ float fast_tanh(float v) {
    float e;
    asm("ex2.approx.f32 %0, %1;" : "=f"(e) : "f"(v * -2.8853900817779268f));
    float r;
    asm("rcp.approx.f32 %0, %1;" : "=f"(r) : "f"(1.0f + e));
    return fmaf(2.0f, r, -1.0f);
}

// One warp (= one 32-thread CTA) processes TWO batch elements.
// lane = hidden unit j (H == 32). The 96 packed W_hh registers depend only on
// lane, so both batches share them; the 6 independent fma2 accumulator chains
// (3 gates x 2 batches) fully pipeline the lat-4/rt-2 FFMA2 stream.
__global__ void __launch_bounds__(32, 7) gru_fused_kernel(
    const float* __restrict__ x,      // [B, T, 1]
    const float* __restrict__ h0,     // [1, B, 32]
    const float* __restrict__ W_ih,   // [96, 1]
    const float* __restrict__ W_hh,   // [96, 32]
    const float* __restrict__ b_ih,   // [96]
    const float* __restrict__ b_hh,   // [96]
    const float* __restrict__ W_out,  // [1, 32]
    const float* __restrict__ b_out,  // [1]
    float* __restrict__ y,            // [B, T, 1]
    float* __restrict__ h_n,          // [1, B, 32]
    int B, int T)
{
    const int lane = threadIdx.x & 31;
    const int b0 = blockIdx.x * 2;
    const int b1 = b0 + 1;
    if (b0 >= B) return;

    __shared__ __align__(16) float hbuf[2][2][32];   // [parity][batch][j]
    __shared__ float ys[2][32][33];                  // [batch][j][s], pad 33

    // ---- packed recurrent weights: 48 x b64 = 96 regs, shared by both batches
    const u64* W2 = (const u64*)W_hh;  // row j = 16 packed pairs
    u64 wr[16], wz[16], wn[16];
#pragma unroll
    for (int p = 0; p < 16; ++p) {
        wr[p] = W2[(0  + lane) * 16 + p];
        wz[p] = W2[(32 + lane) * 16 + p];
        wn[p] = W2[(64 + lane) * 16 + p];
    }
    const float wihr = W_ih[lane], wihz = W_ih[32 + lane], wihn = W_ih[64 + lane];
    const u64 b2r = pack2(b_ih[lane]      + b_hh[lane],      0.0f);
    const u64 b2z = pack2(b_ih[32 + lane] + b_hh[32 + lane], 0.0f);
    const u64 b2n = pack2(b_hh[64 + lane],                   0.0f);
    const float bihn = b_ih[64 + lane];
    const float wout = W_out[lane];
    const float bout = b_out[0];

    const float* xp0 = x + (long long)b0 * T;
    const float* xp1 = x + (long long)b1 * T;
    float*       yp0 = y + (long long)b0 * T;
    float*       yp1 = y + (long long)b1 * T;

    float hj0 = h0[b0 * 32 + lane];
    float hj1 = h0[b1 * 32 + lane];
    hbuf[0][0][lane] = hj0;
    hbuf[0][1][lane] = hj1;
    __syncwarp();

    const int nChunks = T >> 5;       // T multiple of 32
    float xv0 = xp0[lane];            // prefetch chunk 0 (lane-strided)
    float xv1 = xp1[lane];

    for (int c = 0; c < nChunks; ++c) {
        const float xc0 = xv0, xc1 = xv1;
        if (c + 1 < nChunks) {
            xv0 = xp0[(c + 1) * 32 + lane];
            xv1 = xp1[(c + 1) * 32 + lane];
        }

#pragma unroll 2
        for (int s = 0; s < 32; ++s) {
            const int t = (c << 5) + s;
            const int par = t & 1;
            const ulonglong2* ha = (const ulonglong2*)hbuf[par][0];
            const ulonglong2* hb = (const ulonglong2*)hbuf[par][1];

            u64 ar0 = b2r, az0 = b2z, an0 = b2n;
            u64 ar1 = b2r, az1 = b2z, an1 = b2n;
#pragma unroll
            for (int q = 0; q < 8; ++q) {
                const ulonglong2 va = ha[q];   // LDS.128 broadcast
                const ulonglong2 vb = hb[q];
                ar0 = fma2(wr[2 * q],     va.x, ar0);
                ar1 = fma2(wr[2 * q],     vb.x, ar1);
                az0 = fma2(wz[2 * q],     va.x, az0);
                az1 = fma2(wz[2 * q],     vb.x, az1);
                an0 = fma2(wn[2 * q],     va.x, an0);
                an1 = fma2(wn[2 * q],     vb.x, an1);
                ar0 = fma2(wr[2 * q + 1], va.y, ar0);
                ar1 = fma2(wr[2 * q + 1], vb.y, ar1);
                az0 = fma2(wz[2 * q + 1], va.y, az0);
                az1 = fma2(wz[2 * q + 1], vb.y, az1);
                an0 = fma2(wn[2 * q + 1], va.y, an0);
                an1 = fma2(wn[2 * q + 1], vb.y, an1);
            }

            const float xt0 = __shfl_sync(FULL, xc0, s);
            const float xt1 = __shfl_sync(FULL, xc1, s);

            const float r0 = fast_sig(fmaf(xt0, wihr, hadd2(ar0)));
            const float r1 = fast_sig(fmaf(xt1, wihr, hadd2(ar1)));
            const float z0 = fast_sig(fmaf(xt0, wihz, hadd2(az0)));
            const float z1 = fast_sig(fmaf(xt1, wihz, hadd2(az1)));
            const float n0 = fast_tanh(fmaf(r0, hadd2(an0), fmaf(xt0, wihn, bihn)));
            const float n1 = fast_tanh(fmaf(r1, hadd2(an1), fmaf(xt1, wihn, bihn)));

            hj0 = fmaf(z0, hj0 - n0, n0);     // (1-z)*n + z*h
            hj1 = fmaf(z1, hj1 - n1, n1);

            hbuf[par ^ 1][0][lane] = hj0;
            hbuf[par ^ 1][1][lane] = hj1;
            ys[0][lane][s] = hj0 * wout;      // stride-33: conflict-free
            ys[1][lane][s] = hj1 * wout;

            __syncwarp();                     // order STS(h) before next LDS
        }

        // y epilogue: lane l sums column l of ys (conflict-free stride-33 reads)
        {
            float a0 = 0.f, a1 = 0.f, a2 = 0.f, a3 = 0.f;
            float c0 = 0.f, c1 = 0.f, c2 = 0.f, c3 = 0.f;
#pragma unroll
            for (int j = 0; j < 8; ++j) {
                a0 += ys[0][4 * j + 0][lane];
                a1 += ys[0][4 * j + 1][lane];
                a2 += ys[0][4 * j + 2][lane];
                a3 += ys[0][4 * j + 3][lane];
                c0 += ys[1][4 * j + 0][lane];
                c1 += ys[1][4 * j + 1][lane];
                c2 += ys[1][4 * j + 2][lane];
                c3 += ys[1][4 * j + 3][lane];
            }
            yp0[(c << 5) + lane] = (a0 + a1) + (a2 + a3) + bout;
            yp1[(c << 5) + lane] = (c0 + c1) + (c2 + c3) + bout;
        }
        __syncwarp();   // epilogue reads done before next chunk's ys stores
    }

    h_n[b0 * 32 + lane] = hj0;
    h_n[b1 * 32 + lane] = hj1;
}

extern "C" void kernel_launch(void* const* d_in, const int* in_sizes, int n_in,
                              void* d_out, int out_size) {
    const float* x     = (const float*)d_in[0];
    const float* h0    = (const float*)d_in[1];
    const float* W_ih  = (const float*)d_in[2];
    const float* W_hh  = (const float*)d_in[3];
    const float* b_ih  = (const float*)d_in[4];
    const float* b_hh  = (const float*)d_in[5];
    const float* W_out = (const float*)d_in[6];
    const float* b_out = (const float*)d_in[7];

    const int B = in_sizes[1] / 32;      // h_state is [1, B, 32]
    const int T = in_sizes[0] / B;       // x is [B, T, 1]

    float* out = (float*)d_out;
    float* y   = out;                          // [B, T, 1]
    float* h_n = out + (size_t)B * T;          // [1, B, 32]

    const int blocks = (B + 1) / 2;            // 1 warp (2 batches) per CTA
    gru_fused_kernel<<<blocks, 32>>>(x, h0, W_ih, W_hh, b_ih, b_hh,
                                     W_out, b_out, y, h_n, B, T);
}

// round 11
// speedup vs baseline: 1.1986x; 1.1986x over previous
#include <cuda_runtime.h>

#define FULL 0xffffffffu
typedef unsigned long long u64;

__device__ __forceinline__ u64 fma2(u64 a, u64 b, u64 c) {
    u64 d;
    asm("fma.rn.f32x2 %0, %1, %2, %3;" : "=l"(d) : "l"(a), "l"(b), "l"(c));
    return d;
}
__device__ __forceinline__ u64 add2(u64 a, u64 b) {
    u64 d;
    asm("add.rn.f32x2 %0, %1, %2;" : "=l"(d) : "l"(a), "l"(b));
    return d;
}
__device__ __forceinline__ u64 pack2(float lo, float hi) {
    u64 d;
    asm("mov.b64 %0, {%1, %2};" : "=l"(d) : "f"(lo), "f"(hi));
    return d;
}
__device__ __forceinline__ float hadd2(u64 a) {
    float lo, hi;
    asm("mov.b64 {%0, %1}, %2;" : "=f"(lo), "=f"(hi) : "l"(a));
    return lo + hi;
}
// sigmoid(v) = 1 / (1 + 2^(-v*log2e))
__device__ __forceinline__ float fast_sig(float v) {
    float e;
    asm("ex2.approx.f32 %0, %1;" : "=f"(e) : "f"(v * -1.4426950408889634f));
    float r;
    asm("rcp.approx.f32 %0, %1;" : "=f"(r) : "f"(1.0f + e));
    return r;
}
// tanh(v) = 2/(1 + 2^(-2v*log2e)) - 1
__device__ __forceinline__ float fast_tanh(float v) {
    float e;
    asm("ex2.approx.f32 %0, %1;" : "=f"(e) : "f"(v * -2.8853900817779268f));
    float r;
    asm("rcp.approx.f32 %0, %1;" : "=f"(r) : "f"(1.0f + e));
    return fmaf(2.0f, r, -1.0f);
}

#define BAR_SYNC(id)   asm volatile("bar.sync %0, 64;"   :: "r"(id) : "memory")
#define BAR_ARRIVE(id) asm volatile("bar.arrive %0, 64;" :: "r"(id) : "memory")

// One CTA (64 threads = 2 warps) per batch element; lane = hidden unit j.
// Split-K: warp 0 ("lead") accumulates k=0..15, warp 1 ("tail") k=16..31.
// Tail ships packed partial sums through shared; lead combines, runs the
// activations + h update; named arrive/sync barriers (ids 1,2) give each warp
// exactly one wait per step. Tail absorbs the y-epilogue in its slack.
__global__ void __launch_bounds__(64, 10) gru_fused_kernel(
    const float* __restrict__ x,      // [B, T, 1]
    const float* __restrict__ h0,     // [1, B, 32]
    const float* __restrict__ W_ih,   // [96, 1]
    const float* __restrict__ W_hh,   // [96, 32]
    const float* __restrict__ b_ih,   // [96]
    const float* __restrict__ b_hh,   // [96]
    const float* __restrict__ W_out,  // [1, 32]
    const float* __restrict__ b_out,  // [1]
    float* __restrict__ y,            // [B, T, 1]
    float* __restrict__ h_n,          // [1, B, 32]
    int B, int T)
{
    const int lane = threadIdx.x & 31;
    const int warp = threadIdx.x >> 5;   // 0 = lead, 1 = tail
    const int b = blockIdx.x;

    __shared__ __align__(16) float sh_h[32];          // current hidden state
    __shared__ __align__(16) u64   par_rz[32][2];     // tail partials r,z
    __shared__ __align__(16) u64   par_n[32];         // tail partial  n
    __shared__ float ys[32][33];                      // y transpose, pad 33

    // ---- packed recurrent weights for this warp's K-half: 24 x b64 = 48 regs
    const u64* W2 = (const u64*)W_hh;                 // row j = 16 packed pairs
    const int kofs = warp * 8;                        // pair offset of K-half
    u64 wr[8], wz[8], wn[8];
#pragma unroll
    for (int p = 0; p < 8; ++p) {
        wr[p] = W2[(0  + lane) * 16 + kofs + p];
        wz[p] = W2[(32 + lane) * 16 + kofs + p];
        wn[p] = W2[(64 + lane) * 16 + kofs + p];
    }
    // biases folded into lead's accumulator init; tail starts at zero
    const u64 b2r = warp ? 0ull : pack2(b_ih[lane]      + b_hh[lane],      0.0f);
    const u64 b2z = warp ? 0ull : pack2(b_ih[32 + lane] + b_hh[32 + lane], 0.0f);
    const u64 b2n = warp ? 0ull : pack2(b_hh[64 + lane],                   0.0f);
    const float wihr = W_ih[lane], wihz = W_ih[32 + lane], wihn = W_ih[64 + lane];
    const float bihn = b_ih[64 + lane];
    const float wout = W_out[lane];
    const float bout = b_out[0];

    const float* xb = x + (long long)b * T;
    float*       yb = y + (long long)b * T;

    float hj = h0[b * 32 + lane];
    if (warp == 0) sh_h[lane] = hj;
    __syncthreads();

    const int nChunks = T >> 5;                    // T multiple of 32
    float xv = (warp == 0) ? xb[lane] : 0.0f;      // lead prefetches x chunk 0

    // this warp's 64B half of h: 4 LDS.128
    const ulonglong2* hhalf = (const ulonglong2*)(sh_h + warp * 16);

    for (int c = 0; c < nChunks; ++c) {
        const float xcur = xv;
        if (warp == 0 && c + 1 < nChunks) xv = xb[(c + 1) * 32 + lane];

#pragma unroll 2
        for (int s = 0; s < 32; ++s) {
            u64 ar = b2r, az = b2z, an = b2n;
#pragma unroll
            for (int q = 0; q < 4; ++q) {
                const ulonglong2 v = hhalf[q];     // LDS.128 broadcast
                ar = fma2(wr[2 * q],     v.x, ar);
                az = fma2(wz[2 * q],     v.x, az);
                an = fma2(wn[2 * q],     v.x, an);
                ar = fma2(wr[2 * q + 1], v.y, ar);
                az = fma2(wz[2 * q + 1], v.y, az);
                an = fma2(wn[2 * q + 1], v.y, an);
            }

            if (warp) {
                // tail: publish partials, hand off to lead, wait for new h
                par_rz[lane][0] = ar;              // STS.128
                par_rz[lane][1] = az;
                par_n[lane]     = an;              // STS.64
                BAR_ARRIVE(1);
                BAR_SYNC(2);                       // new h visible after this
            } else {
                BAR_SYNC(1);                       // tail partials ready
                const u64 art = add2(ar, par_rz[lane][0]);   // LDS.128
                const u64 azt = add2(az, par_rz[lane][1]);
                const u64 ant = add2(an, par_n[lane]);       // LDS.64

                const float xt = __shfl_sync(FULL, xcur, s);
                const float r = fast_sig(fmaf(xt, wihr, hadd2(art)));
                const float z = fast_sig(fmaf(xt, wihz, hadd2(azt)));
                const float n = fast_tanh(fmaf(r, hadd2(ant),
                                               fmaf(xt, wihn, bihn)));
                hj = fmaf(z, hj - n, n);           // (1-z)*n + z*h
                sh_h[lane]   = hj;
                ys[lane][s]  = hj * wout;          // stride-33, conflict-free
                __syncwarp();                      // own-warp h visibility
                BAR_ARRIVE(2);                     // release tail (drains STS)
            }
        }

        if (warp) {
            // tail: y epilogue in its slack — lane l sums column l of ys
            float a0 = 0.f, a1 = 0.f, a2 = 0.f, a3 = 0.f;
#pragma unroll
            for (int j = 0; j < 8; ++j) {
                a0 += ys[4 * j + 0][lane];
                a1 += ys[4 * j + 1][lane];
                a2 += ys[4 * j + 2][lane];
                a3 += ys[4 * j + 3][lane];
            }
            yb[(c << 5) + lane] = (a0 + a1) + (a2 + a3) + bout;
            // lead's next ys write waits on bar.sync(1) <- our NEXT arrive(1),
            // which is after these reads, so no race with chunk c+1.
        }
    }

    if (warp == 0) h_n[b * 32 + lane] = hj;
}

extern "C" void kernel_launch(void* const* d_in, const int* in_sizes, int n_in,
                              void* d_out, int out_size) {
    const float* x     = (const float*)d_in[0];
    const float* h0    = (const float*)d_in[1];
    const float* W_ih  = (const float*)d_in[2];
    const float* W_hh  = (const float*)d_in[3];
    const float* b_ih  = (const float*)d_in[4];
    const float* b_hh  = (const float*)d_in[5];
    const float* W_out = (const float*)d_in[6];
    const float* b_out = (const float*)d_in[7];

    const int B = in_sizes[1] / 32;      // h_state is [1, B, 32]
    const int T = in_sizes[0] / B;       // x is [B, T, 1]

    float* out = (float*)d_out;
    float* y   = out;                          // [B, T, 1]
    float* h_n = out + (size_t)B * T;          // [1, B, 32]

    gru_fused_kernel<<<B, 64>>>(x, h0, W_ih, W_hh, b_ih, b_hh,
                                W_out, b_out, y, h_n, B, T);
}

// round 15
// speedup vs baseline: 1.5254x; 1.2727x over previous
#include <cuda_runtime.h>

#define FULL 0xffffffffu
typedef unsigned long long u64;

__device__ __forceinline__ u64 fma2(u64 a, u64 b, u64 c) {
    u64 d;
    asm("fma.rn.f32x2 %0, %1, %2, %3;" : "=l"(d) : "l"(a), "l"(b), "l"(c));
    return d;
}
__device__ __forceinline__ u64 add2(u64 a, u64 b) {
    u64 d;
    asm("add.rn.f32x2 %0, %1, %2;" : "=l"(d) : "l"(a), "l"(b));
    return d;
}
__device__ __forceinline__ u64 pack2(float lo, float hi) {
    u64 d;
    asm("mov.b64 %0, {%1, %2};" : "=l"(d) : "f"(lo), "f"(hi));
    return d;
}
__device__ __forceinline__ float hadd2(u64 a) {
    float lo, hi;
    asm("mov.b64 {%0, %1}, %2;" : "=f"(lo), "=f"(hi) : "l"(a));  // reg-pair alias: free
    return lo + hi;
}
// sigmoid(v) = 1 / (1 + 2^(-v*log2e))
__device__ __forceinline__ float fast_sig(float v) {
    float e;
    asm("ex2.approx.f32 %0, %1;" : "=f"(e) : "f"(v * -1.4426950408889634f));
    float r;
    asm("rcp.approx.f32 %0, %1;" : "=f"(r) : "f"(1.0f + e));
    return r;
}
// tanh(v) = 2/(1 + 2^(-2v*log2e)) - 1
__device__ __forceinline__ float fast_tanh(float v) {
    float e;
    asm("ex2.approx.f32 %0, %1;" : "=f"(e) : "f"(v * -2.8853900817779268f));
    float r;
    asm("rcp.approx.f32 %0, %1;" : "=f"(r) : "f"(1.0f + e));
    return fmaf(2.0f, r, -1.0f);
}

// One 32-thread CTA = one warp = one batch element; lane = hidden unit j.
// No cross-warp sync ever. Per step: 8x LDS.128 broadcast of h, 6 independent
// 8-deep fma2 chains (3 gates x even/odd split), activations, h STS, one ys STS.
// y reduced per 32-step chunk via a padded shared transpose (no SHFL butterfly).
__global__ void __launch_bounds__(32, 14) gru_fused_kernel(
    const float* __restrict__ x,      // [B, T, 1]
    const float* __restrict__ h0,     // [1, B, 32]
    const float* __restrict__ W_ih,   // [96, 1]
    const float* __restrict__ W_hh,   // [96, 32]
    const float* __restrict__ b_ih,   // [96]
    const float* __restrict__ b_hh,   // [96]
    const float* __restrict__ W_out,  // [1, 32]
    const float* __restrict__ b_out,  // [1]
    float* __restrict__ y,            // [B, T, 1]
    float* __restrict__ h_n,          // [1, B, 32]
    int B, int T)
{
    const int lane = threadIdx.x & 31;
    const int b = blockIdx.x;

    __shared__ __align__(16) float hbuf[2][32];   // double-buffered h
    __shared__ float ys[32][33];                  // [j][s], pad 33: conflict-free

    // ---- packed recurrent weights: 48 x b64 = 96 regs ----
    const u64* W2 = (const u64*)W_hh;  // row j = 16 packed pairs
    u64 wr[16], wz[16], wn[16];
#pragma unroll
    for (int p = 0; p < 16; ++p) {
        wr[p] = W2[(0  + lane) * 16 + p];
        wz[p] = W2[(32 + lane) * 16 + p];
        wn[p] = W2[(64 + lane) * 16 + p];
    }
    const float wihr = W_ih[lane], wihz = W_ih[32 + lane], wihn = W_ih[64 + lane];
    const u64 b2r = pack2(b_ih[lane]      + b_hh[lane],      0.0f);
    const u64 b2z = pack2(b_ih[32 + lane] + b_hh[32 + lane], 0.0f);
    const u64 b2n = pack2(b_hh[64 + lane],                   0.0f);
    const float bihn = b_ih[64 + lane];
    const float wout = W_out[lane];
    const float bout = b_out[0];

    const float* xb = x + (long long)b * T;
    float*       yb = y + (long long)b * T;

    float hj = h0[b * 32 + lane];
    hbuf[0][lane] = hj;
    __syncwarp();

    const int nChunks = T >> 5;   // T multiple of 32
    float xv = xb[lane];          // prefetch chunk 0 (lane-strided x)

    for (int c = 0; c < nChunks; ++c) {
        const float xcur = xv;
        if (c + 1 < nChunks) xv = xb[(c + 1) * 32 + lane];

#pragma unroll 4
        for (int s = 0; s < 32; ++s) {
            const int t = (c << 5) + s;
            const ulonglong2* h4 = (const ulonglong2*)hbuf[t & 1];

            // 6 independent 8-deep chains: 3 gates x (even,odd) pairs
            u64 are = b2r, azo = 0ull, aze = b2z, aro = 0ull, ane = b2n, ano = 0ull;
#pragma unroll
            for (int q = 0; q < 8; ++q) {
                const ulonglong2 v = h4[q];        // LDS.128 broadcast
                are = fma2(wr[2 * q],     v.x, are);
                aze = fma2(wz[2 * q],     v.x, aze);
                ane = fma2(wn[2 * q],     v.x, ane);
                aro = fma2(wr[2 * q + 1], v.y, aro);
                azo = fma2(wz[2 * q + 1], v.y, azo);
                ano = fma2(wn[2 * q + 1], v.y, ano);
            }
            const u64 ar = add2(are, aro);
            const u64 az = add2(aze, azo);
            const u64 an = add2(ane, ano);

            const float xt = __shfl_sync(FULL, xcur, s);
            const float r = fast_sig(fmaf(xt, wihr, hadd2(ar)));
            const float z = fast_sig(fmaf(xt, wihz, hadd2(az)));
            const float n = fast_tanh(fmaf(r, hadd2(an), fmaf(xt, wihn, bihn)));

            hj = fmaf(z, hj - n, n);               // (1-z)*n + z*h
            hbuf[(t + 1) & 1][lane] = hj;
            ys[lane][s] = hj * wout;               // stride-33, conflict-free

            __syncwarp();                          // order STS(h) before next LDS
        }

        // y epilogue: lane l sums column l of ys (conflict-free, 4-way ILP)
        {
            float a0 = 0.f, a1 = 0.f, a2 = 0.f, a3 = 0.f;
#pragma unroll
            for (int j = 0; j < 8; ++j) {
                a0 += ys[4 * j + 0][lane];
                a1 += ys[4 * j + 1][lane];
                a2 += ys[4 * j + 2][lane];
                a3 += ys[4 * j + 3][lane];
            }
            yb[(c << 5) + lane] = (a0 + a1) + (a2 + a3) + bout;  // coalesced
        }
        __syncwarp();   // epilogue reads done before next chunk's ys stores
    }

    h_n[b * 32 + lane] = hj;
}

extern "C" void kernel_launch(void* const* d_in, const int* in_sizes, int n_in,
                              void* d_out, int out_size) {
    const float* x     = (const float*)d_in[0];
    const float* h0    = (const float*)d_in[1];
    const float* W_ih  = (const float*)d_in[2];
    const float* W_hh  = (const float*)d_in[3];
    const float* b_ih  = (const float*)d_in[4];
    const float* b_hh  = (const float*)d_in[5];
    const float* W_out = (const float*)d_in[6];
    const float* b_out = (const float*)d_in[7];

    const int B = in_sizes[1] / 32;      // h_state is [1, B, 32]
    const int T = in_sizes[0] / B;       // x is [B, T, 1]

    float* out = (float*)d_out;
    float* y   = out;                          // [B, T, 1]
    float* h_n = out + (size_t)B * T;          // [1, B, 32]

    gru_fused_kernel<<<B, 32>>>(x, h0, W_ih, W_hh, b_ih, b_hh,
                                W_out, b_out, y, h_n, B, T);
}